// round 1
// baseline (speedup 1.0000x reference)
#include <cuda_runtime.h>
#include <math.h>

// Problem constants
#define BB   256
#define TT   1000
#define HH   64
#define GG   256   // 4*H
#define DIN  22
#define DH   128   // 2*H
#define TILE_B 4

// Scratch (device globals; no runtime allocation allowed)
__device__ float g_xw[(size_t)2 * BB * TT * GG];      // [dir][b][t][g]  524 MB
__device__ float g_hbuf[2][(size_t)BB * TT * DH];     // ping-pong layer outputs

__device__ __forceinline__ float fast_sig(float x) {
    return __fdividef(1.0f, 1.0f + __expf(-x));
}
__device__ __forceinline__ float fast_tanh(float x) {
    return __fdividef(2.0f, 1.0f + __expf(-2.0f * x)) - 1.0f;
}

// ---------------------------------------------------------------------------
// Layer-0 input projection: xw[dir][b][t][g] = sum_d x[b][d][t]*W[dir][g][d] + bias
// grid (B, 2), 256 threads (one per gate row g)
// ---------------------------------------------------------------------------
__global__ __launch_bounds__(256) void gemm0_kernel(
    const float* __restrict__ x,       // (B, 22, T)
    const float* __restrict__ w,       // (2, 256, 22)
    const float* __restrict__ bih,     // (4, 2, 256)
    const float* __restrict__ bhh)     // (4, 2, 256)
{
    const int b = blockIdx.x, dir = blockIdx.y;
    const int g = threadIdx.x;
    __shared__ float xs[DIN][16];

    float wr[DIN];
#pragma unroll
    for (int d = 0; d < DIN; d++) wr[d] = w[(dir * GG + g) * DIN + d];
    const float bias = bih[dir * GG + g] + bhh[dir * GG + g];

    const float* xb = x + (size_t)b * DIN * TT;
    float* out = g_xw + ((size_t)(dir * BB + b)) * TT * GG;

    for (int tc = 0; tc < TT; tc += 16) {
        for (int e = threadIdx.x; e < DIN * 16; e += 256) {
            int d = e >> 4, tt = e & 15;
            int t = tc + tt;
            xs[d][tt] = (t < TT) ? xb[d * TT + t] : 0.0f;
        }
        __syncthreads();
        float acc[16];
#pragma unroll
        for (int tt = 0; tt < 16; tt++) acc[tt] = bias;
#pragma unroll
        for (int d = 0; d < DIN; d++) {
            float wd = wr[d];
#pragma unroll
            for (int tt = 0; tt < 16; tt++) acc[tt] = fmaf(wd, xs[d][tt], acc[tt]);
        }
#pragma unroll
        for (int tt = 0; tt < 16; tt++) {
            int t = tc + tt;
            if (t < TT) out[(size_t)t * GG + g] = acc[tt];
        }
        __syncthreads();
    }
}

// ---------------------------------------------------------------------------
// Layers 1..3 input projection: D = 128. grid (B, 2), 256 threads.
// smem: W [256][132] padded + x chunk [16][128]
// ---------------------------------------------------------------------------
#define GEMM_SMEM ((256 * 132 + 16 * 128) * 4)

__global__ __launch_bounds__(256) void gemm_rest_kernel(
    const float* __restrict__ w,       // (3, 2, 256, 128)
    const float* __restrict__ bih,     // (4, 2, 256)
    const float* __restrict__ bhh,
    int layer, int insel)
{
    extern __shared__ float sm[];
    float* Ws = sm;                    // [256][132]
    float* xs = sm + 256 * 132;        // [16][128]

    const int b = blockIdx.x, dir = blockIdx.y;
    const int g = threadIdx.x;

    const float* wp = w + ((size_t)((layer - 1) * 2 + dir)) * GG * DH;
    for (int e = threadIdx.x; e < GG * DH; e += 256)
        Ws[(e >> 7) * 132 + (e & 127)] = wp[e];

    const float bias = bih[(layer * 2 + dir) * GG + g] + bhh[(layer * 2 + dir) * GG + g];
    const float* inb = g_hbuf[insel] + (size_t)b * TT * DH;
    float* out = g_xw + ((size_t)(dir * BB + b)) * TT * GG;
    __syncthreads();

    for (int tc = 0; tc < TT; tc += 16) {
        for (int e = threadIdx.x; e < 16 * DH; e += 256) {
            int tt = e >> 7, d = e & 127;
            int t = tc + tt;
            xs[e] = (t < TT) ? inb[(size_t)t * DH + d] : 0.0f;
        }
        __syncthreads();

        float acc[16];
#pragma unroll
        for (int tt = 0; tt < 16; tt++) acc[tt] = bias;

        const float4* wrow = (const float4*)(Ws + g * 132);
#pragma unroll
        for (int d4 = 0; d4 < 32; d4++) {
            float4 w4 = wrow[d4];
#pragma unroll
            for (int tt = 0; tt < 16; tt++) {
                float4 x4 = *(const float4*)(xs + tt * 128 + d4 * 4);
                acc[tt] = fmaf(w4.x, x4.x, acc[tt]);
                acc[tt] = fmaf(w4.y, x4.y, acc[tt]);
                acc[tt] = fmaf(w4.z, x4.z, acc[tt]);
                acc[tt] = fmaf(w4.w, x4.w, acc[tt]);
            }
        }
#pragma unroll
        for (int tt = 0; tt < 16; tt++) {
            int t = tc + tt;
            if (t < TT) out[(size_t)t * GG + g] = acc[tt];
        }
        __syncthreads();
    }
}

// ---------------------------------------------------------------------------
// Recurrent scan. grid (B/TILE_B, 2), 256 threads (one per gate row).
// Phase A: thread g computes gates for TILE_B batches. Phase B: thread
// (b, j) updates c (register) and h (smem + gmem).
// ---------------------------------------------------------------------------
#define RECUR_SMEM ((256 * 68 + TILE_B * 64 + TILE_B * 256) * 4)

__global__ __launch_bounds__(256) void lstm_recur_kernel(
    const float* __restrict__ whh,     // (4, 2, 256, 64)
    int layer, int outsel)
{
    extern __shared__ float sm[];
    float* Wt = sm;                          // [256][68] padded
    float* hs = sm + 256 * 68;               // [TILE_B][64]
    float* gs = hs + TILE_B * 64;            // [TILE_B][256]

    const int dir = blockIdx.y;
    const int b0 = blockIdx.x * TILE_B;
    const int g = threadIdx.x;

    const float* wp = whh + ((size_t)(layer * 2 + dir)) * GG * HH;
    for (int e = threadIdx.x; e < GG * HH; e += 256)
        Wt[(e >> 6) * 68 + (e & 63)] = wp[e];
    hs[threadIdx.x] = 0.0f;   // TILE_B*64 == 256
    __syncthreads();

    const float* xwb = g_xw + ((size_t)(dir * BB + b0)) * TT * GG;
    float* hout = g_hbuf[outsel];
    const int gtype = g >> 6;
    const int bb = g >> 6, jj = g & 63;
    float c = 0.0f;

    const float4* wrow = (const float4*)(Wt + g * 68);

    for (int s = 0; s < TT; s++) {
        const int t = dir ? (TT - 1 - s) : s;

        // prefetch xw for this (t, g) across the 4 batches (latency hidden by FMA loop)
        float xw0 = xwb[((size_t)0 * TT + t) * GG + g];
        float xw1 = xwb[((size_t)1 * TT + t) * GG + g];
        float xw2 = xwb[((size_t)2 * TT + t) * GG + g];
        float xw3 = xwb[((size_t)3 * TT + t) * GG + g];

        float a0 = 0.f, a1 = 0.f, a2 = 0.f, a3 = 0.f;
#pragma unroll
        for (int k4 = 0; k4 < 16; k4++) {
            float4 w4 = wrow[k4];
            float4 h0 = *(const float4*)(hs + 0 * 64 + k4 * 4);
            float4 h1 = *(const float4*)(hs + 1 * 64 + k4 * 4);
            float4 h2 = *(const float4*)(hs + 2 * 64 + k4 * 4);
            float4 h3 = *(const float4*)(hs + 3 * 64 + k4 * 4);
            a0 = fmaf(w4.x, h0.x, a0); a0 = fmaf(w4.y, h0.y, a0);
            a0 = fmaf(w4.z, h0.z, a0); a0 = fmaf(w4.w, h0.w, a0);
            a1 = fmaf(w4.x, h1.x, a1); a1 = fmaf(w4.y, h1.y, a1);
            a1 = fmaf(w4.z, h1.z, a1); a1 = fmaf(w4.w, h1.w, a1);
            a2 = fmaf(w4.x, h2.x, a2); a2 = fmaf(w4.y, h2.y, a2);
            a2 = fmaf(w4.z, h2.z, a2); a2 = fmaf(w4.w, h2.w, a2);
            a3 = fmaf(w4.x, h3.x, a3); a3 = fmaf(w4.y, h3.y, a3);
            a3 = fmaf(w4.z, h3.z, a3); a3 = fmaf(w4.w, h3.w, a3);
        }
        a0 += xw0; a1 += xw1; a2 += xw2; a3 += xw3;

        float v0, v1, v2, v3;
        if (gtype == 2) {
            v0 = fast_tanh(a0); v1 = fast_tanh(a1);
            v2 = fast_tanh(a2); v3 = fast_tanh(a3);
        } else {
            v0 = fast_sig(a0); v1 = fast_sig(a1);
            v2 = fast_sig(a2); v3 = fast_sig(a3);
        }
        gs[0 * 256 + g] = v0;
        gs[1 * 256 + g] = v1;
        gs[2 * 256 + g] = v2;
        gs[3 * 256 + g] = v3;
        __syncthreads();

        // Phase B: thread (bb, jj) owns c
        {
            float vi = gs[bb * 256 + jj];
            float vf = gs[bb * 256 + 64 + jj];
            float vg = gs[bb * 256 + 128 + jj];
            float vo = gs[bb * 256 + 192 + jj];
            c = vf * c + vi * vg;
            float h = vo * fast_tanh(c);
            hs[bb * 64 + jj] = h;
            hout[(((size_t)(b0 + bb)) * TT + t) * DH + dir * HH + jj] = h;
        }
        __syncthreads();
    }
}

// ---------------------------------------------------------------------------
// Final linear head on last timestep of layer-3 output (g_hbuf[1]).
// ---------------------------------------------------------------------------
__global__ __launch_bounds__(64) void head_kernel(
    const float* __restrict__ wl,      // (54, 128)
    const float* __restrict__ bl,      // (54,)
    float* __restrict__ out)           // (B, 54)
{
    const int b = blockIdx.x;
    __shared__ float hsm[DH];
    const int tid = threadIdx.x;
    const float* hin = g_hbuf[1];
    for (int e = tid; e < DH; e += 64)
        hsm[e] = hin[((size_t)b * TT + (TT - 1)) * DH + e];
    __syncthreads();
    if (tid < 54) {
        float acc = bl[tid];
#pragma unroll
        for (int k = 0; k < DH; k++) acc = fmaf(hsm[k], wl[tid * DH + k], acc);
        out[b * 54 + tid] = acc;
    }
}

// ---------------------------------------------------------------------------
extern "C" void kernel_launch(void* const* d_in, const int* in_sizes, int n_in,
                              void* d_out, int out_size)
{
    (void)in_sizes; (void)n_in; (void)out_size;
    const float* x      = (const float*)d_in[0];
    const float* w_ih_f = (const float*)d_in[1];
    const float* w_ih_r = (const float*)d_in[2];
    const float* w_hh   = (const float*)d_in[3];
    const float* b_ih   = (const float*)d_in[4];
    const float* b_hh   = (const float*)d_in[5];
    const float* w_lin  = (const float*)d_in[6];
    const float* b_lin  = (const float*)d_in[7];
    float* out = (float*)d_out;

    cudaFuncSetAttribute(gemm_rest_kernel,
                         cudaFuncAttributeMaxDynamicSharedMemorySize, GEMM_SMEM);
    cudaFuncSetAttribute(lstm_recur_kernel,
                         cudaFuncAttributeMaxDynamicSharedMemorySize, RECUR_SMEM);

    dim3 gridG(BB, 2);
    dim3 gridR(BB / TILE_B, 2);

    // Layer 0
    gemm0_kernel<<<gridG, 256>>>(x, w_ih_f, b_ih, b_hh);
    lstm_recur_kernel<<<gridR, 256, RECUR_SMEM>>>(w_hh, 0, 0);

    // Layers 1..3
    for (int l = 1; l < 4; l++) {
        gemm_rest_kernel<<<gridG, 256, GEMM_SMEM>>>(w_ih_r, b_ih, b_hh, l, (l - 1) & 1);
        lstm_recur_kernel<<<gridR, 256, RECUR_SMEM>>>(w_hh, l, l & 1);
    }

    // Head
    head_kernel<<<BB, 64>>>(w_lin, b_lin, out);
}

// round 2
// speedup vs baseline: 1.6081x; 1.6081x over previous
#include <cuda_runtime.h>
#include <math.h>

// Problem constants
#define BB   256
#define TT   1000
#define HH   64
#define GG   256   // 4*H
#define DIN  22
#define DH   128   // 2*H
#define RTILE 4    // batches per recurrent block

// Scratch (device globals; no runtime allocation allowed)
__device__ float g_xw[(size_t)2 * BB * TT * GG];      // [dir][b][t][g]
__device__ float g_hbuf[2][(size_t)BB * TT * DH];     // ping-pong layer outputs

typedef unsigned long long u64;

__device__ __forceinline__ float fast_sig(float x) {
    return __fdividef(1.0f, 1.0f + __expf(-x));
}
__device__ __forceinline__ float fast_tanh(float x) {
    return __fdividef(2.0f, 1.0f + __expf(-2.0f * x)) - 1.0f;
}

// ---- packed f32x2 helpers (FFMA2 pattern; exact fp32 math) ----
__device__ __forceinline__ u64 pack2(float lo, float hi) {
    u64 r; asm("mov.b64 %0, {%1, %2};" : "=l"(r) : "f"(lo), "f"(hi)); return r;
}
__device__ __forceinline__ void unpack2(u64 v, float& lo, float& hi) {
    asm("mov.b64 {%0, %1}, %2;" : "=f"(lo), "=f"(hi) : "l"(v));
}
__device__ __forceinline__ u64 splat2(float x) {
    u64 r; asm("mov.b64 %0, {%1, %1};" : "=l"(r) : "f"(x)); return r;
}
__device__ __forceinline__ u64 fma2(u64 a, u64 b, u64 c) {
    u64 d; asm("fma.rn.f32x2 %0, %1, %2, %3;" : "=l"(d) : "l"(a), "l"(b), "l"(c));
    return d;
}

// ---------------------------------------------------------------------------
// Layer-0 input projection: xw[dir][b][t][g] = sum_d x[b][d][t]*W[dir][g][d] + bias
// grid (B, 2), 256 threads (one per gate row g)
// ---------------------------------------------------------------------------
__global__ __launch_bounds__(256) void gemm0_kernel(
    const float* __restrict__ x,       // (B, 22, T)
    const float* __restrict__ w,       // (2, 256, 22)
    const float* __restrict__ bih,     // (4, 2, 256)
    const float* __restrict__ bhh)     // (4, 2, 256)
{
    const int b = blockIdx.x, dir = blockIdx.y;
    const int g = threadIdx.x;
    __shared__ float xs[DIN][16];

    float wr[DIN];
#pragma unroll
    for (int d = 0; d < DIN; d++) wr[d] = w[(dir * GG + g) * DIN + d];
    const float bias = bih[dir * GG + g] + bhh[dir * GG + g];

    const float* xb = x + (size_t)b * DIN * TT;
    float* out = g_xw + ((size_t)(dir * BB + b)) * TT * GG;

    for (int tc = 0; tc < TT; tc += 16) {
        for (int e = threadIdx.x; e < DIN * 16; e += 256) {
            int d = e >> 4, tt = e & 15;
            int t = tc + tt;
            xs[d][tt] = (t < TT) ? xb[d * TT + t] : 0.0f;
        }
        __syncthreads();
        float acc[16];
#pragma unroll
        for (int tt = 0; tt < 16; tt++) acc[tt] = bias;
#pragma unroll
        for (int d = 0; d < DIN; d++) {
            float wd = wr[d];
#pragma unroll
            for (int tt = 0; tt < 16; tt++) acc[tt] = fmaf(wd, xs[d][tt], acc[tt]);
        }
#pragma unroll
        for (int tt = 0; tt < 16; tt++) {
            int t = tc + tt;
            if (t < TT) out[(size_t)t * GG + g] = acc[tt];
        }
        __syncthreads();
    }
}

// ---------------------------------------------------------------------------
// Layers 1..3 input projection, register-tiled with f32x2 FMA.
// grid (B, 2, 2): (batch, dir, t-half). 256 threads.
// Thread tile: 4 gates x 16 timesteps. Two gate-halves (g0, g0+128).
// smem: Wt transposed [128 k][260 pad] + xst transposed [128 k][132 pad]
// ---------------------------------------------------------------------------
#define WT_STRIDE 260
#define XS_STRIDE 132
#define GEMM_SMEM ((128 * WT_STRIDE + 128 * XS_STRIDE) * 4)

__global__ __launch_bounds__(256) void gemm_rest_kernel(
    const float* __restrict__ w,       // (3, 2, 256, 128)
    const float* __restrict__ bih,     // (4, 2, 256)
    const float* __restrict__ bhh,
    int layer, int insel)
{
    extern __shared__ float sm[];
    float* Wt  = sm;                       // [128][260]
    float* xst = sm + 128 * WT_STRIDE;     // [128][132]
    __shared__ float bsm[GG];

    const int b = blockIdx.x, dir = blockIdx.y, z = blockIdx.z;
    const int tid = threadIdx.x;
    const int gq = tid & 31;      // 32 gate-quads
    const int tq = tid >> 5;      // 8 t-groups of 16

    // Stage W transposed: Wt[k][g] = W[g][k]
    const float* wp = w + ((size_t)((layer - 1) * 2 + dir)) * GG * DH;
    for (int e = tid; e < GG * DH; e += 256) {
        int g = e >> 7, k = e & 127;
        Wt[k * WT_STRIDE + g] = wp[e];
    }
    bsm[tid] = bih[(layer * 2 + dir) * GG + tid] + bhh[(layer * 2 + dir) * GG + tid];

    const float* inb = g_hbuf[insel] + (size_t)b * TT * DH;
    float* outp = g_xw + ((size_t)(dir * BB + b)) * TT * GG;

    const int tbase = z * 500;
    const int tend  = tbase + 500;
    __syncthreads();

    for (int tc = tbase; tc < tend; tc += 128) {
        // Stage x transposed: xst[d][tt] = in[tc+tt][d]
        for (int e = tid; e < 128 * 128; e += 256) {
            int tt = e >> 7, d = e & 127;
            int t = tc + tt;
            xst[d * XS_STRIDE + tt] = (t < tend) ? inb[(size_t)t * DH + d] : 0.0f;
        }
        __syncthreads();

        for (int gh = 0; gh < 2; gh++) {
            const int g0 = gh * 128 + 4 * gq;
            u64 acc[4][8];
#pragma unroll
            for (int g = 0; g < 4; g++) {
                u64 bsp = splat2(bsm[g0 + g]);
#pragma unroll
                for (int tp = 0; tp < 8; tp++) acc[g][tp] = bsp;
            }

#pragma unroll 2
            for (int k = 0; k < 128; k++) {
                float4 w4 = *(const float4*)(Wt + k * WT_STRIDE + g0);
                const ulonglong2* xp =
                    (const ulonglong2*)(xst + k * XS_STRIDE + tq * 16);
                ulonglong2 xA = xp[0], xB = xp[1], xC = xp[2], xD = xp[3];
                u64 x2[8] = {xA.x, xA.y, xB.x, xB.y, xC.x, xC.y, xD.x, xD.y};
                u64 ws[4] = {splat2(w4.x), splat2(w4.y), splat2(w4.z), splat2(w4.w)};
#pragma unroll
                for (int g = 0; g < 4; g++)
#pragma unroll
                    for (int tp = 0; tp < 8; tp++)
                        acc[g][tp] = fma2(x2[tp], ws[g], acc[g][tp]);
            }

            // Store: per timestep, 4 contiguous gates -> float4
#pragma unroll
            for (int tp = 0; tp < 8; tp++) {
                float lo[4], hi[4];
#pragma unroll
                for (int g = 0; g < 4; g++) unpack2(acc[g][tp], lo[g], hi[g]);
                int t0 = tc + tq * 16 + 2 * tp;
                if (t0 < tend)
                    *(float4*)(outp + (size_t)t0 * GG + g0) =
                        make_float4(lo[0], lo[1], lo[2], lo[3]);
                if (t0 + 1 < tend)
                    *(float4*)(outp + (size_t)(t0 + 1) * GG + g0) =
                        make_float4(hi[0], hi[1], hi[2], hi[3]);
            }
        }
        __syncthreads();
    }
}

// ---------------------------------------------------------------------------
// Recurrent scan. grid (B/RTILE, 2), 256 threads.
// Phase A: thread (gg,bg) owns gates 2gg,2gg+1 for batch pair {2bg,2bg+1};
//          W rows live in registers; h read as packed batch-pair float4
//          broadcasts; math in f32x2.
// Phase B: thread (b,j) owns cell state c.
// ---------------------------------------------------------------------------
__global__ __launch_bounds__(256, 1) void lstm_recur_kernel(
    const float* __restrict__ whh,     // (4, 2, 256, 64)
    int layer, int outsel)
{
    // hs_p[bp][2k + (b&1)] : batch-pair-interleaved h
    __shared__ float hs_p[2 * 128];
    __shared__ float gs[RTILE * 256];

    const int dir = blockIdx.y;
    const int b0 = blockIdx.x * RTILE;
    const int tid = threadIdx.x;
    const int gg = tid & 127, bg = tid >> 7;
    const int ga = 2 * gg;                // first of this thread's gate pair
    const int bB = tid >> 6, jj = tid & 63;   // phase-B identity
    const int gtype = ga >> 6;            // 0:i 1:f 2:g 3:o

    // W rows for the two gates into registers
    float wa[64], wb[64];
    const float* wpa = whh + ((size_t)(layer * 2 + dir)) * GG * HH + (size_t)ga * HH;
#pragma unroll
    for (int k = 0; k < 64; k++) { wa[k] = wpa[k]; wb[k] = wpa[64 + k]; }

    hs_p[tid] = 0.0f;   // 256 == 2*128
    float c = 0.0f;

    const float* xwb = g_xw + ((size_t)(dir * BB + b0)) * TT * GG;
    float* hout = g_hbuf[outsel];
    __syncthreads();

    // prefetch xw for step 0
    int tp0 = dir ? (TT - 1) : 0;
    float2 xwP0 = *(const float2*)(xwb + ((size_t)(2 * bg) * TT + tp0) * GG + ga);
    float2 xwP1 = *(const float2*)(xwb + ((size_t)(2 * bg + 1) * TT + tp0) * GG + ga);

    const float* hp = hs_p + bg * 128;

    for (int s = 0; s < TT; s++) {
        const int t = dir ? (TT - 1 - s) : s;
        float2 cx0 = xwP0, cx1 = xwP1;
        if (s + 1 < TT) {
            int tn = dir ? (t - 1) : (t + 1);
            xwP0 = *(const float2*)(xwb + ((size_t)(2 * bg) * TT + tn) * GG + ga);
            xwP1 = *(const float2*)(xwb + ((size_t)(2 * bg + 1) * TT + tn) * GG + ga);
        }

        // acc packs (batch 2bg | batch 2bg+1)
        u64 acc_a = pack2(cx0.x, cx1.x);
        u64 acc_b = pack2(cx0.y, cx1.y);
#pragma unroll
        for (int k2 = 0; k2 < 32; k2++) {
            ulonglong2 h4 = *(const ulonglong2*)(hp + 4 * k2);
            acc_a = fma2(h4.x, splat2(wa[2 * k2]),     acc_a);
            acc_a = fma2(h4.y, splat2(wa[2 * k2 + 1]), acc_a);
            acc_b = fma2(h4.x, splat2(wb[2 * k2]),     acc_b);
            acc_b = fma2(h4.y, splat2(wb[2 * k2 + 1]), acc_b);
        }
        float aa0, aa1, ab0, ab1;
        unpack2(acc_a, aa0, aa1);
        unpack2(acc_b, ab0, ab1);

        float va0, va1, vb0, vb1;
        if (gtype == 2) {
            va0 = fast_tanh(aa0); va1 = fast_tanh(aa1);
            vb0 = fast_tanh(ab0); vb1 = fast_tanh(ab1);
        } else {
            va0 = fast_sig(aa0); va1 = fast_sig(aa1);
            vb0 = fast_sig(ab0); vb1 = fast_sig(ab1);
        }
        *(float2*)(gs + (2 * bg) * 256 + ga)     = make_float2(va0, vb0);
        *(float2*)(gs + (2 * bg + 1) * 256 + ga) = make_float2(va1, vb1);
        __syncthreads();

        // Phase B
        {
            float vi = gs[bB * 256 + jj];
            float vf = gs[bB * 256 + 64 + jj];
            float vg = gs[bB * 256 + 128 + jj];
            float vo = gs[bB * 256 + 192 + jj];
            c = vf * c + vi * vg;
            float h = vo * fast_tanh(c);
            hs_p[(bB >> 1) * 128 + 2 * jj + (bB & 1)] = h;
            hout[(((size_t)(b0 + bB)) * TT + t) * DH + dir * HH + jj] = h;
        }
        __syncthreads();
    }
}

// ---------------------------------------------------------------------------
// Final linear head on last timestep of layer-3 output (g_hbuf[1]).
// ---------------------------------------------------------------------------
__global__ __launch_bounds__(64) void head_kernel(
    const float* __restrict__ wl,      // (54, 128)
    const float* __restrict__ bl,      // (54,)
    float* __restrict__ out)           // (B, 54)
{
    const int b = blockIdx.x;
    __shared__ float hsm[DH];
    const int tid = threadIdx.x;
    const float* hin = g_hbuf[1];
    for (int e = tid; e < DH; e += 64)
        hsm[e] = hin[((size_t)b * TT + (TT - 1)) * DH + e];
    __syncthreads();
    if (tid < 54) {
        float acc = bl[tid];
#pragma unroll
        for (int k = 0; k < DH; k++) acc = fmaf(hsm[k], wl[tid * DH + k], acc);
        out[b * 54 + tid] = acc;
    }
}

// ---------------------------------------------------------------------------
extern "C" void kernel_launch(void* const* d_in, const int* in_sizes, int n_in,
                              void* d_out, int out_size)
{
    (void)in_sizes; (void)n_in; (void)out_size;
    const float* x      = (const float*)d_in[0];
    const float* w_ih_f = (const float*)d_in[1];
    const float* w_ih_r = (const float*)d_in[2];
    const float* w_hh   = (const float*)d_in[3];
    const float* b_ih   = (const float*)d_in[4];
    const float* b_hh   = (const float*)d_in[5];
    const float* w_lin  = (const float*)d_in[6];
    const float* b_lin  = (const float*)d_in[7];
    float* out = (float*)d_out;

    cudaFuncSetAttribute(gemm_rest_kernel,
                         cudaFuncAttributeMaxDynamicSharedMemorySize, GEMM_SMEM);

    dim3 grid0(BB, 2);
    dim3 gridG(BB, 2, 2);
    dim3 gridR(BB / RTILE, 2);

    // Layer 0
    gemm0_kernel<<<grid0, 256>>>(x, w_ih_f, b_ih, b_hh);
    lstm_recur_kernel<<<gridR, 256>>>(w_hh, 0, 0);

    // Layers 1..3
    for (int l = 1; l < 4; l++) {
        gemm_rest_kernel<<<gridG, 256, GEMM_SMEM>>>(w_ih_r, b_ih, b_hh, l, (l - 1) & 1);
        lstm_recur_kernel<<<gridR, 256>>>(w_hh, l, l & 1);
    }

    // Head
    head_kernel<<<BB, 64>>>(w_lin, b_lin, out);
}

// round 3
// speedup vs baseline: 1.9839x; 1.2337x over previous
#include <cuda_runtime.h>
#include <math.h>

// Problem constants
#define BB   256
#define TT   1000
#define HH   64
#define GG   256   // 4*H
#define DIN  22
#define DH   128   // 2*H

// Scratch (device globals; no runtime allocation allowed)
__device__ float g_xw[(size_t)2 * BB * TT * GG];      // [dir][b][t][g]
__device__ float g_hbuf[2][(size_t)BB * TT * DH];     // ping-pong layer outputs

typedef unsigned long long u64;

__device__ __forceinline__ float fast_sig(float x) {
    return __fdividef(1.0f, 1.0f + __expf(-x));
}
__device__ __forceinline__ float fast_tanh(float x) {
    return __fdividef(2.0f, 1.0f + __expf(-2.0f * x)) - 1.0f;
}

// ---- packed f32x2 helpers (FFMA2 pattern; exact fp32 math) ----
__device__ __forceinline__ u64 pack2(float lo, float hi) {
    u64 r; asm("mov.b64 %0, {%1, %2};" : "=l"(r) : "f"(lo), "f"(hi)); return r;
}
__device__ __forceinline__ void unpack2(u64 v, float& lo, float& hi) {
    asm("mov.b64 {%0, %1}, %2;" : "=f"(lo), "=f"(hi) : "l"(v));
}
__device__ __forceinline__ u64 splat2(float x) {
    u64 r; asm("mov.b64 %0, {%1, %1};" : "=l"(r) : "f"(x)); return r;
}
__device__ __forceinline__ u64 fma2(u64 a, u64 b, u64 c) {
    u64 d; asm("fma.rn.f32x2 %0, %1, %2, %3;" : "=l"(d) : "l"(a), "l"(b), "l"(c));
    return d;
}
// shuffle-xor both halves of a packed f32x2 and add
__device__ __forceinline__ u64 shfl_add2(u64 v, int m) {
    float lo, hi; unpack2(v, lo, hi);
    float lo2 = __shfl_xor_sync(0xFFFFFFFFu, lo, m);
    float hi2 = __shfl_xor_sync(0xFFFFFFFFu, hi, m);
    return pack2(lo + lo2, hi + hi2);
}

// ---------------------------------------------------------------------------
// Layer-0 input projection: xw[dir][b][t][g] = sum_d x[b][d][t]*W[dir][g][d] + bias
// grid (B, 2), 256 threads (one per gate row g)
// ---------------------------------------------------------------------------
__global__ __launch_bounds__(256) void gemm0_kernel(
    const float* __restrict__ x,       // (B, 22, T)
    const float* __restrict__ w,       // (2, 256, 22)
    const float* __restrict__ bih,     // (4, 2, 256)
    const float* __restrict__ bhh)     // (4, 2, 256)
{
    const int b = blockIdx.x, dir = blockIdx.y;
    const int g = threadIdx.x;
    __shared__ float xs[DIN][16];

    float wr[DIN];
#pragma unroll
    for (int d = 0; d < DIN; d++) wr[d] = w[(dir * GG + g) * DIN + d];
    const float bias = bih[dir * GG + g] + bhh[dir * GG + g];

    const float* xb = x + (size_t)b * DIN * TT;
    float* out = g_xw + ((size_t)(dir * BB + b)) * TT * GG;

    for (int tc = 0; tc < TT; tc += 16) {
        for (int e = threadIdx.x; e < DIN * 16; e += 256) {
            int d = e >> 4, tt = e & 15;
            int t = tc + tt;
            xs[d][tt] = (t < TT) ? xb[d * TT + t] : 0.0f;
        }
        __syncthreads();
        float acc[16];
#pragma unroll
        for (int tt = 0; tt < 16; tt++) acc[tt] = bias;
#pragma unroll
        for (int d = 0; d < DIN; d++) {
            float wd = wr[d];
#pragma unroll
            for (int tt = 0; tt < 16; tt++) acc[tt] = fmaf(wd, xs[d][tt], acc[tt]);
        }
#pragma unroll
        for (int tt = 0; tt < 16; tt++) {
            int t = tc + tt;
            if (t < TT) out[(size_t)t * GG + g] = acc[tt];
        }
        __syncthreads();
    }
}

// ---------------------------------------------------------------------------
// Layers 1..3 input projection, register-tiled f32x2, 512 threads.
// grid (B, 2, 2): (batch, dir, t-half).
// Thread: (gh, tq, gq) -> 4 gates x 16 timesteps.
// smem: Wt transposed [128 k][260 pad] + xst transposed [128 k][132 pad]
// ---------------------------------------------------------------------------
#define WT_STRIDE 260
#define XS_STRIDE 132
#define GEMM_SMEM ((128 * WT_STRIDE + 128 * XS_STRIDE) * 4)

__global__ __launch_bounds__(512) void gemm_rest_kernel(
    const float* __restrict__ w,       // (3, 2, 256, 128)
    const float* __restrict__ bih,     // (4, 2, 256)
    const float* __restrict__ bhh,
    int layer, int insel)
{
    extern __shared__ float sm[];
    float* Wt  = sm;                       // [128][260]
    float* xst = sm + 128 * WT_STRIDE;     // [128][132]
    __shared__ float bsm[GG];

    const int b = blockIdx.x, dir = blockIdx.y, z = blockIdx.z;
    const int tid = threadIdx.x;
    const int gq = tid & 31;           // 32 gate-quads within half
    const int tq = (tid >> 5) & 7;     // 8 t-groups of 16
    const int gh = tid >> 8;           // gate half
    const int g0 = gh * 128 + 4 * gq;

    // Stage W transposed: Wt[k][g] = W[g][k]
    const float* wp = w + ((size_t)((layer - 1) * 2 + dir)) * GG * DH;
    for (int e = tid; e < GG * DH; e += 512) {
        int g = e >> 7, k = e & 127;
        Wt[k * WT_STRIDE + g] = wp[e];
    }
    if (tid < GG)
        bsm[tid] = bih[(layer * 2 + dir) * GG + tid] + bhh[(layer * 2 + dir) * GG + tid];

    const float* inb = g_hbuf[insel] + (size_t)b * TT * DH;
    float* outp = g_xw + ((size_t)(dir * BB + b)) * TT * GG;

    const int tbase = z * 500;
    const int tend  = tbase + 500;
    __syncthreads();

    for (int tc = tbase; tc < tend; tc += 128) {
        // Stage x transposed: xst[d][tt] = in[tc+tt][d]
        for (int e = tid; e < 128 * 128; e += 512) {
            int tt = e >> 7, d = e & 127;
            int t = tc + tt;
            xst[d * XS_STRIDE + tt] = (t < tend) ? inb[(size_t)t * DH + d] : 0.0f;
        }
        __syncthreads();

        u64 acc[4][8];
#pragma unroll
        for (int g = 0; g < 4; g++) {
            u64 bsp = splat2(bsm[g0 + g]);
#pragma unroll
            for (int tp = 0; tp < 8; tp++) acc[g][tp] = bsp;
        }

#pragma unroll 2
        for (int k = 0; k < 128; k++) {
            float4 w4 = *(const float4*)(Wt + k * WT_STRIDE + g0);
            const ulonglong2* xp =
                (const ulonglong2*)(xst + k * XS_STRIDE + tq * 16);
            ulonglong2 xA = xp[0], xB = xp[1], xC = xp[2], xD = xp[3];
            u64 x2[8] = {xA.x, xA.y, xB.x, xB.y, xC.x, xC.y, xD.x, xD.y};
            u64 ws[4] = {splat2(w4.x), splat2(w4.y), splat2(w4.z), splat2(w4.w)};
#pragma unroll
            for (int g = 0; g < 4; g++)
#pragma unroll
                for (int tp = 0; tp < 8; tp++)
                    acc[g][tp] = fma2(x2[tp], ws[g], acc[g][tp]);
        }

        // Store: per timestep, 4 contiguous gates -> float4
#pragma unroll
        for (int tp = 0; tp < 8; tp++) {
            float lo[4], hi[4];
#pragma unroll
            for (int g = 0; g < 4; g++) unpack2(acc[g][tp], lo[g], hi[g]);
            int t0 = tc + tq * 16 + 2 * tp;
            if (t0 < tend)
                *(float4*)(outp + (size_t)t0 * GG + g0) =
                    make_float4(lo[0], lo[1], lo[2], lo[3]);
            if (t0 + 1 < tend)
                *(float4*)(outp + (size_t)(t0 + 1) * GG + g0) =
                    make_float4(hi[0], hi[1], hi[2], hi[3]);
        }
        __syncthreads();
    }
}

// ---------------------------------------------------------------------------
// Recurrent scan v3. grid (B/4, 2), 512 threads, ONE barrier per step.
// Thread = (j 0..63, bp 0..1, ks 0..3): all 4 gates for hidden unit j,
// batch pair (2bp, 2bp+1), k-slice [16ks, 16ks+16). Gate-pair-packed f32x2,
// W in registers, k-reduction via shfl_xor(8,16). Lane ks<2 owns the cell
// update for batch 2bp+ks. h kept duplicated (h,h) in bank-padded,
// double-buffered smem.
// ---------------------------------------------------------------------------
#define HS_BSTRIDE 144   // floats per batch row (64 units * 2 dup + 4*4 pad)
#define HS_BUF     (4 * HS_BSTRIDE)

__global__ __launch_bounds__(512, 1) void lstm_recur_kernel(
    const float* __restrict__ whh,     // (4, 2, 256, 64)
    int layer, int outsel)
{
    __shared__ float hs2[2 * HS_BUF];  // double buffer

    const int dir = blockIdx.y;
    const int b0 = blockIdx.x * 4;
    const int tid = threadIdx.x;
    const int lane = tid & 31;
    const int j_lo = lane & 7;
    const int ks   = lane >> 3;          // k-slice 0..3
    const int wrp  = tid >> 5;
    const int j_hi = wrp & 7;
    const int bp   = wrp >> 3;           // batch pair 0..1
    const int j    = j_hi * 8 + j_lo;    // hidden unit 0..63

    // W rows for 4 gates, gate-pair packed, k-slice only: 32 u64 regs
    u64 wp01[16], wp23[16];
    {
        const float* wb = whh + (size_t)(layer * 2 + dir) * GG * HH;
#pragma unroll
        for (int kk = 0; kk < 16; kk++) {
            int k = ks * 16 + kk;
            wp01[kk] = pack2(wb[(j)       * HH + k], wb[(64 + j)  * HH + k]);
            wp23[kk] = pack2(wb[(128 + j) * HH + k], wb[(192 + j) * HH + k]);
        }
    }

    for (int e = tid; e < 2 * HS_BUF; e += 512) hs2[e] = 0.0f;

    const bool act = (ks < 2);
    const int bl = 2 * bp + (ks & 1);    // local batch this lane owns (if act)
    const float* xwp = g_xw + ((size_t)(dir * BB + b0 + bl)) * TT * GG + j;
    float* houtp = g_hbuf[outsel] + ((size_t)(b0 + bl)) * TT * DH + dir * HH + j;
    float c = 0.0f;

    __syncthreads();

    // prefetch xw for step 0
    float nx_i = 0.f, nx_f = 0.f, nx_g = 0.f, nx_o = 0.f;
    {
        int t0 = dir ? (TT - 1) : 0;
        if (act) {
            const float* xp = xwp + (size_t)t0 * GG;
            nx_i = xp[0]; nx_f = xp[64]; nx_g = xp[128]; nx_o = xp[192];
        }
    }

    const int rdoff = (2 * bp) * HS_BSTRIDE + ks * 36;   // read base within buffer
    const int wroff = bl * HS_BSTRIDE + (j >> 4) * 36 + (j & 15) * 2;

    for (int s = 0; s < TT; s++) {
        const int t = dir ? (TT - 1 - s) : s;
        float cx_i = nx_i, cx_f = nx_f, cx_g = nx_g, cx_o = nx_o;
        if (act && s + 1 < TT) {
            int tn = dir ? (t - 1) : (t + 1);
            const float* xp = xwp + (size_t)tn * GG;
            nx_i = xp[0]; nx_f = xp[64]; nx_g = xp[128]; nx_o = xp[192];
        }

        const float* h0p = hs2 + ((s + 1) & 1) * HS_BUF + rdoff;
        const float* h1p = h0p + HS_BSTRIDE;

        u64 z2 = pack2(0.f, 0.f);
        u64 a01_0 = z2, a23_0 = z2, a01_1 = z2, a23_1 = z2;
#pragma unroll
        for (int q = 0; q < 8; q++) {
            ulonglong2 hh0 = *(const ulonglong2*)(h0p + 4 * q);
            ulonglong2 hh1 = *(const ulonglong2*)(h1p + 4 * q);
            a01_0 = fma2(hh0.x, wp01[2 * q],     a01_0);
            a01_0 = fma2(hh0.y, wp01[2 * q + 1], a01_0);
            a23_0 = fma2(hh0.x, wp23[2 * q],     a23_0);
            a23_0 = fma2(hh0.y, wp23[2 * q + 1], a23_0);
            a01_1 = fma2(hh1.x, wp01[2 * q],     a01_1);
            a01_1 = fma2(hh1.y, wp01[2 * q + 1], a01_1);
            a23_1 = fma2(hh1.x, wp23[2 * q],     a23_1);
            a23_1 = fma2(hh1.y, wp23[2 * q + 1], a23_1);
        }

        // reduce partial k-sums across the 4 k-slices (lanes xor 8, 16)
        a01_0 = shfl_add2(a01_0, 8); a01_0 = shfl_add2(a01_0, 16);
        a23_0 = shfl_add2(a23_0, 8); a23_0 = shfl_add2(a23_0, 16);
        a01_1 = shfl_add2(a01_1, 8); a01_1 = shfl_add2(a01_1, 16);
        a23_1 = shfl_add2(a23_1, 8); a23_1 = shfl_add2(a23_1, 16);

        if (act) {
            u64 a01 = (ks & 1) ? a01_1 : a01_0;
            u64 a23 = (ks & 1) ? a23_1 : a23_0;
            float ai, af, ag, ao;
            unpack2(a01, ai, af);
            unpack2(a23, ag, ao);
            ai += cx_i; af += cx_f; ag += cx_g; ao += cx_o;
            float gi = fast_sig(ai);
            float gf = fast_sig(af);
            float gv = fast_tanh(ag);
            float go = fast_sig(ao);
            c = gf * c + gi * gv;
            float h = go * fast_tanh(c);
            *(float2*)(hs2 + (s & 1) * HS_BUF + wroff) = make_float2(h, h);
            houtp[(size_t)t * DH] = h;
        }
        __syncthreads();
    }
}

// ---------------------------------------------------------------------------
// Final linear head on last timestep of layer-3 output (g_hbuf[1]).
// ---------------------------------------------------------------------------
__global__ __launch_bounds__(64) void head_kernel(
    const float* __restrict__ wl,      // (54, 128)
    const float* __restrict__ bl,      // (54,)
    float* __restrict__ out)           // (B, 54)
{
    const int b = blockIdx.x;
    __shared__ float hsm[DH];
    const int tid = threadIdx.x;
    const float* hin = g_hbuf[1];
    for (int e = tid; e < DH; e += 64)
        hsm[e] = hin[((size_t)b * TT + (TT - 1)) * DH + e];
    __syncthreads();
    if (tid < 54) {
        float acc = bl[tid];
#pragma unroll
        for (int k = 0; k < DH; k++) acc = fmaf(hsm[k], wl[tid * DH + k], acc);
        out[b * 54 + tid] = acc;
    }
}

// ---------------------------------------------------------------------------
extern "C" void kernel_launch(void* const* d_in, const int* in_sizes, int n_in,
                              void* d_out, int out_size)
{
    (void)in_sizes; (void)n_in; (void)out_size;
    const float* x      = (const float*)d_in[0];
    const float* w_ih_f = (const float*)d_in[1];
    const float* w_ih_r = (const float*)d_in[2];
    const float* w_hh   = (const float*)d_in[3];
    const float* b_ih   = (const float*)d_in[4];
    const float* b_hh   = (const float*)d_in[5];
    const float* w_lin  = (const float*)d_in[6];
    const float* b_lin  = (const float*)d_in[7];
    float* out = (float*)d_out;

    cudaFuncSetAttribute(gemm_rest_kernel,
                         cudaFuncAttributeMaxDynamicSharedMemorySize, GEMM_SMEM);

    dim3 grid0(BB, 2);
    dim3 gridG(BB, 2, 2);
    dim3 gridR(BB / 4, 2);

    // Layer 0
    gemm0_kernel<<<grid0, 256>>>(x, w_ih_f, b_ih, b_hh);
    lstm_recur_kernel<<<gridR, 512>>>(w_hh, 0, 0);

    // Layers 1..3
    for (int l = 1; l < 4; l++) {
        gemm_rest_kernel<<<gridG, 512, GEMM_SMEM>>>(w_ih_r, b_ih, b_hh, l, (l - 1) & 1);
        lstm_recur_kernel<<<gridR, 512>>>(w_hh, l, l & 1);
    }

    // Head
    head_kernel<<<BB, 64>>>(w_lin, b_lin, out);
}